// round 1
// baseline (speedup 1.0000x reference)
#include <cuda_runtime.h>
#include <math_constants.h>

// Global-max scratch (ordered-uint encoding so atomicMax works for signed floats)
__device__ unsigned g_max_ordered;

__device__ __forceinline__ unsigned order_f32(float f) {
    unsigned u = __float_as_uint(f);
    return (u & 0x80000000u) ? ~u : (u | 0x80000000u);
}
__device__ __forceinline__ float unorder_f32(unsigned u) {
    return __uint_as_float((u & 0x80000000u) ? (u ^ 0x80000000u) : ~u);
}

__global__ void init_kernel() {
    g_max_ordered = 0u;  // encodes below any real float
}

// One block per row. Warp h (0..6) scans head h's row: top-2 + target value.
// Warps 0..5 also contribute their row-max (== top1) to the global max.
__global__ __launch_bounds__(256) void margin_softmax_kernel(
    const float* __restrict__ o1, const float* __restrict__ o2,
    const float* __restrict__ o3, const float* __restrict__ o4,
    const float* __restrict__ o5, const float* __restrict__ o6,
    const float* __restrict__ mimic,
    const int* __restrict__ targets,
    float* __restrict__ out_thresh,   // [N,7]
    int C)
{
    const int row  = blockIdx.x;
    const int wid  = threadIdx.x >> 5;
    const int lane = threadIdx.x & 31;

    __shared__ float s_margin[7];
    __shared__ unsigned s_maxu;
    if (threadIdx.x == 0) s_maxu = 0u;
    __syncthreads();

    if (wid < 7) {
        const float* heads[7] = {o1, o2, o3, o4, o5, o6, mimic};
        const float* p = heads[wid] + (size_t)row * (size_t)C;

        float t1 = -CUDART_INF_F, t2 = -CUDART_INF_F;

        const int nv4 = C >> 2;                     // C=1000 -> 250 float4
        const float4* p4 = (const float4*)p;       // row byte offset 4000*row, 16B aligned
        for (int i = lane; i < nv4; i += 32) {
            float4 v = p4[i];
            t2 = fmaxf(t2, fminf(t1, v.x)); t1 = fmaxf(t1, v.x);
            t2 = fmaxf(t2, fminf(t1, v.y)); t1 = fmaxf(t1, v.y);
            t2 = fmaxf(t2, fminf(t1, v.z)); t1 = fmaxf(t1, v.z);
            t2 = fmaxf(t2, fminf(t1, v.w)); t1 = fmaxf(t1, v.w);
        }
        // tail (C % 4 != 0) — not hit for C=1000 but kept for safety
        for (int i = (nv4 << 2) + lane; i < C; i += 32) {
            float v = p[i];
            t2 = fmaxf(t2, fminf(t1, v)); t1 = fmaxf(t1, v);
        }

        // warp top-2 reduction
        #pragma unroll
        for (int off = 16; off; off >>= 1) {
            float u1 = __shfl_down_sync(0xFFFFFFFFu, t1, off);
            float u2 = __shfl_down_sync(0xFFFFFFFFu, t2, off);
            t2 = fmaxf(fmaxf(t2, u2), fminf(t1, u1));
            t1 = fmaxf(t1, u1);
        }

        if (lane == 0) {
            float tval = __ldg(p + targets[row]);
            s_margin[wid] = (tval == t1) ? (t1 - t2) : 0.0f;
            if (wid < 6) atomicMax(&s_maxu, order_f32(t1));
        }
    }
    __syncthreads();

    if (threadIdx.x == 0) {
        if (s_maxu) atomicMax(&g_max_ordered, s_maxu);
        // 7-way softmax of margins / TEMPERATURE (=2)
        float m[7], mx = -CUDART_INF_F;
        #pragma unroll
        for (int h = 0; h < 7; ++h) { m[h] = s_margin[h] * 0.5f; mx = fmaxf(mx, m[h]); }
        float e[7], sum = 0.0f;
        #pragma unroll
        for (int h = 0; h < 7; ++h) { e[h] = __expf(m[h] - mx); sum += e[h]; }
        float inv = 1.0f / sum;
        float* o = out_thresh + (size_t)row * 7;
        #pragma unroll
        for (int h = 0; h < 7; ++h) o[h] = e[h] * inv;
    }
}

__global__ void finalize_kernel(float* __restrict__ out) {
    out[0] = unorder_f32(g_max_ordered);
}

extern "C" void kernel_launch(void* const* d_in, const int* in_sizes, int n_in,
                              void* d_out, int out_size) {
    const float* o1    = (const float*)d_in[0];
    const float* o2    = (const float*)d_in[1];
    const float* o3    = (const float*)d_in[2];
    const float* o4    = (const float*)d_in[3];
    const float* o5    = (const float*)d_in[4];
    const float* o6    = (const float*)d_in[5];
    const float* mimic = (const float*)d_in[6];
    const int*   tgt   = (const int*)d_in[7];

    const int N = in_sizes[7];            // 16384 rows (targets count)
    const int C = in_sizes[0] / N;        // 1000 classes

    float* out = (float*)d_out;           // [0] = max_preds, [1..] = thresholds [N,7]

    init_kernel<<<1, 1>>>();
    margin_softmax_kernel<<<N, 256>>>(o1, o2, o3, o4, o5, o6, mimic, tgt, out + 1, C);
    finalize_kernel<<<1, 1>>>(out);
}